// round 1
// baseline (speedup 1.0000x reference)
// ColdDiffusion q_sample with anchor matching.
// Kernel 1 (scan): nearest-anchor search per (point, anchor-chunk) using packed
//   fp32x2 FFMA2 (Blackwell) with reference-matching rounding order.
// Kernel 2 (finalize): reduce chunk partials, gather anchor, blend output.
#include <cuda_runtime.h>

#define D        8
#define M_ANCH   8192
#define BQ       16
#define NQ       2048
#define P_TOTAL  (BQ * NQ)      // 32768 points
#define CHUNK    512            // anchors per CTA chunk
#define NCHUNK   (M_ANCH / CHUNK)   // 16
#define PAIRS    (CHUNK / 2)    // 256
#define PG       256            // points per CTA
#define NPG      (P_TOTAL / PG) // 128

typedef unsigned long long u64;

// Partial results: [chunk][point] for coalesced writes and reads.
__device__ float g_pscore[NCHUNK * P_TOTAL];
__device__ int   g_pidx[NCHUNK * P_TOTAL];

__device__ __forceinline__ u64 pack2(float lo, float hi) {
    u64 r; asm("mov.b64 %0, {%1,%2};" : "=l"(r) : "f"(lo), "f"(hi)); return r;
}
__device__ __forceinline__ void unpack2(u64 v, float& lo, float& hi) {
    asm("mov.b64 {%0,%1}, %2;" : "=f"(lo), "=f"(hi) : "l"(v));
}
// Packed fp32x2 fused multiply-add (SASS FFMA2) — per-half round-to-nearest,
// bitwise identical to scalar FFMA per lane.
__device__ __forceinline__ u64 fma2(u64 a, u64 b, u64 c) {
    u64 d; asm("fma.rn.f32x2 %0, %1, %2, %3;" : "=l"(d) : "l"(a), "l"(b), "l"(c)); return d;
}

__global__ __launch_bounds__(PG) void scan_kernel(const float* __restrict__ x,
                                                  const float* __restrict__ anchors) {
    // s_pair[j*8+k] = (a[2j][k], a[2j+1][k]) for local pair j (16B-aligned for LDS.128)
    __shared__ __align__(16) u64 s_pair[PAIRS * D];
    __shared__ __align__(16) u64 s_norm[PAIRS];   // (||a_2j||^2, ||a_2j+1||^2)

    const int tid   = threadIdx.x;
    const int pg    = blockIdx.x % NPG;
    const int ch    = blockIdx.x / NPG;
    const int abase = ch * CHUNK;

    // ---- pack this chunk's anchors into SMEM (pair-interleaved, k-major) ----
    const float* A = anchors + (size_t)abase * D;
    for (int i = tid; i < CHUNK * D; i += PG) {
        int j = i >> 3, k = i & 7;
        ((float*)&s_pair[(j >> 1) * D + k])[j & 1] = A[i];
    }
    // norms: sequential sum of individually-rounded squares (matches XLA reduce)
    for (int j = tid; j < CHUNK; j += PG) {
        const float* a = A + j * D;
        float n = __fmul_rn(a[0], a[0]);
        #pragma unroll
        for (int k = 1; k < D; k++) n = __fadd_rn(n, __fmul_rn(a[k], a[k]));
        ((float*)&s_norm[j >> 1])[j & 1] = n;
    }
    __syncthreads();

    // ---- per-thread point: broadcast-scan all pairs in this chunk ----
    const int point = pg * PG + tid;
    u64 xx[D];
    {
        const float4* xp = (const float4*)(x + (size_t)point * D);
        float4 x0 = xp[0], x1 = xp[1];
        xx[0] = pack2(x0.x, x0.x); xx[1] = pack2(x0.y, x0.y);
        xx[2] = pack2(x0.z, x0.z); xx[3] = pack2(x0.w, x0.w);
        xx[4] = pack2(x1.x, x1.x); xx[5] = pack2(x1.y, x1.y);
        xx[6] = pack2(x1.z, x1.z); xx[7] = pack2(x1.w, x1.w);
    }
    const u64 NEG2 = pack2(-2.0f, -2.0f);

    float best = 3.402823466e38f;
    int   bidx = 0;

    #pragma unroll 4
    for (int p = 0; p < PAIRS; p++) {
        const ulonglong2* q = (const ulonglong2*)&s_pair[p * D];
        ulonglong2 q0 = q[0], q1 = q[1], q2 = q[2], q3 = q[3];
        // dot = sum_k x_k * a_k, ascending k, sequential FMA chain (cuBLAS order)
        u64 acc = fma2(xx[0], q0.x, 0ull);
        acc = fma2(xx[1], q0.y, acc);
        acc = fma2(xx[2], q1.x, acc);
        acc = fma2(xx[3], q1.y, acc);
        acc = fma2(xx[4], q2.x, acc);
        acc = fma2(xx[5], q2.y, acc);
        acc = fma2(xx[6], q3.x, acc);
        acc = fma2(xx[7], q3.y, acc);
        // score = norm - 2*dot ; exact: -2*dot is a power-of-two scale, so
        // fma(dot,-2,norm) == round(norm + round(-2*dot)) == reference.
        u64 s2 = fma2(acc, NEG2, s_norm[p]);
        float slo, shi; unpack2(s2, slo, shi);
        int ib = abase + 2 * p;
        float m = slo; int ii = ib;
        if (shi < slo) { m = shi; ii = ib + 1; }   // tie -> even (lower) index
        if (m < best)  { best = m; bidx = ii; }    // tie -> earlier index
    }

    g_pscore[ch * P_TOTAL + point] = best;
    g_pidx  [ch * P_TOTAL + point] = bidx;
}

__global__ __launch_bounds__(256) void finalize_kernel(const float* __restrict__ x,
                                                       const float* __restrict__ anchors,
                                                       const float* __restrict__ sa_tab,
                                                       const float* __restrict__ sb_tab,
                                                       const int* __restrict__ t,
                                                       float* __restrict__ out) {
    const int point = blockIdx.x * blockDim.x + threadIdx.x;
    if (point >= P_TOTAL) return;

    float best = 3.402823466e38f;
    int   bidx = 0;
    #pragma unroll
    for (int c = 0; c < NCHUNK; c++) {      // ascending chunk (=index) order
        float s = g_pscore[c * P_TOTAL + point];
        int   i = g_pidx  [c * P_TOTAL + point];
        if (s < best) { best = s; bidx = i; }
    }

    const int b  = point / NQ;
    const int tb = t[b];
    const float sa = sa_tab[tb];
    const float sb = sb_tab[tb];

    const float4* xp = (const float4*)(x + (size_t)point * D);
    const float4* ap = (const float4*)(anchors + (size_t)bidx * D);
    float4 x0 = xp[0], x1 = xp[1];
    float4 a0 = ap[0], a1 = ap[1];
    float4 o0, o1;
    // out = round(sa*x) + round(sb*a), no FMA contraction (matches reference)
    o0.x = __fadd_rn(__fmul_rn(sa, x0.x), __fmul_rn(sb, a0.x));
    o0.y = __fadd_rn(__fmul_rn(sa, x0.y), __fmul_rn(sb, a0.y));
    o0.z = __fadd_rn(__fmul_rn(sa, x0.z), __fmul_rn(sb, a0.z));
    o0.w = __fadd_rn(__fmul_rn(sa, x0.w), __fmul_rn(sb, a0.w));
    o1.x = __fadd_rn(__fmul_rn(sa, x1.x), __fmul_rn(sb, a1.x));
    o1.y = __fadd_rn(__fmul_rn(sa, x1.y), __fmul_rn(sb, a1.y));
    o1.z = __fadd_rn(__fmul_rn(sa, x1.z), __fmul_rn(sb, a1.z));
    o1.w = __fadd_rn(__fmul_rn(sa, x1.w), __fmul_rn(sb, a1.w));

    float4* op = (float4*)(out + (size_t)point * D);
    op[0] = o0; op[1] = o1;
}

extern "C" void kernel_launch(void* const* d_in, const int* in_sizes, int n_in,
                              void* d_out, int out_size) {
    const float* x       = (const float*)d_in[0];  // [16,2048,4,2]
    const float* anchors = (const float*)d_in[1];  // [8192,4,2]
    const float* sa_tab  = (const float*)d_in[2];  // [1000]
    const float* sb_tab  = (const float*)d_in[3];  // [1000]
    const int*   t       = (const int*)d_in[4];    // [16]
    float*       out     = (float*)d_out;          // [16,2048,4,2]

    scan_kernel<<<NPG * NCHUNK, PG>>>(x, anchors);
    finalize_kernel<<<P_TOTAL / 256, 256>>>(x, anchors, sa_tab, sb_tab, t, out);
}

// round 2
// speedup vs baseline: 1.3099x; 1.3099x over previous
// ColdDiffusion q_sample with anchor matching — Round 2.
// scan: 2 points/thread amortize shared-memory anchor loads over 2x FFMA2 work
//       (fma-pipe bound). Per-chunk result folded via red.min.u64 on a
//       sortable (score,idx) key -> no partial arrays, exact first-index ties.
// init: reset the per-point best keys (graph-replay safe).
// finalize: unpack winner, gather anchor, blend (reference rounding order).
#include <cuda_runtime.h>

#define D        8
#define M_ANCH   8192
#define BQ       16
#define NQ       2048
#define P_TOTAL  (BQ * NQ)          // 32768 points
#define CHUNK    512                // anchors per CTA chunk
#define NCHUNK   (M_ANCH / CHUNK)   // 16
#define PAIRS    (CHUNK / 2)        // 256
#define TPB      256                // threads per CTA
#define PPT      2                  // points per thread
#define PPC      (TPB * PPT)        // 512 points per CTA
#define NPG      (P_TOTAL / PPC)    // 64 point groups
#define FLT_BIG  3.402823466e38f

typedef unsigned long long u64;

// Per-point best (sortable_score<<32 | anchor_idx); min == reference argmin.
__device__ u64 g_best[P_TOTAL];

__device__ __forceinline__ u64 pack2(float lo, float hi) {
    u64 r; asm("mov.b64 %0, {%1,%2};" : "=l"(r) : "f"(lo), "f"(hi)); return r;
}
__device__ __forceinline__ void unpack2(u64 v, float& lo, float& hi) {
    asm("mov.b64 {%0,%1}, %2;" : "=f"(lo), "=f"(hi) : "l"(v));
}
// Packed fp32x2 FMA (SASS FFMA2) — per-half round-to-nearest, bitwise identical
// to scalar FFMA per lane.
__device__ __forceinline__ u64 fma2(u64 a, u64 b, u64 c) {
    u64 d; asm("fma.rn.f32x2 %0, %1, %2, %3;" : "=l"(d) : "l"(a), "l"(b), "l"(c)); return d;
}
// Monotone float -> uint map (total order preserved; no NaNs in this data).
__device__ __forceinline__ unsigned sortable(float f) {
    unsigned u = __float_as_uint(f);
    return (u & 0x80000000u) ? ~u : (u | 0x80000000u);
}

__global__ __launch_bounds__(TPB) void init_kernel() {
    int i = blockIdx.x * blockDim.x + threadIdx.x;
    if (i < P_TOTAL) g_best[i] = 0xFFFFFFFFFFFFFFFFull;
}

__global__ __launch_bounds__(TPB) void scan_kernel(const float* __restrict__ x,
                                                   const float* __restrict__ anchors) {
    // s_pair[j*8+k] = (a[2j][k], a[2j+1][k]) pair-interleaved, k-major (LDS.128-friendly)
    __shared__ __align__(16) u64 s_pair[PAIRS * D];
    __shared__ __align__(16) u64 s_norm[PAIRS];   // (||a_2j||^2, ||a_2j+1||^2)

    const int tid   = threadIdx.x;
    const int pg    = blockIdx.x % NPG;
    const int ch    = blockIdx.x / NPG;
    const int abase = ch * CHUNK;

    // ---- pack this chunk's anchors into SMEM ----
    const float* A = anchors + (size_t)abase * D;
    for (int i = tid; i < CHUNK * D; i += TPB) {
        int j = i >> 3, k = i & 7;
        ((float*)&s_pair[(j >> 1) * D + k])[j & 1] = A[i];
    }
    // norms: sequential sum of individually-rounded squares (reference order)
    for (int j = tid; j < CHUNK; j += TPB) {
        const float* a = A + j * D;
        float n = __fmul_rn(a[0], a[0]);
        #pragma unroll
        for (int k = 1; k < D; k++) n = __fadd_rn(n, __fmul_rn(a[k], a[k]));
        ((float*)&s_norm[j >> 1])[j & 1] = n;
    }
    __syncthreads();

    // ---- two points per thread ----
    const int point0 = pg * PPC + tid;
    const int point1 = point0 + TPB;
    u64 xa[D], xb[D];
    {
        const float4* xp = (const float4*)(x + (size_t)point0 * D);
        float4 v0 = xp[0], v1 = xp[1];
        xa[0] = pack2(v0.x, v0.x); xa[1] = pack2(v0.y, v0.y);
        xa[2] = pack2(v0.z, v0.z); xa[3] = pack2(v0.w, v0.w);
        xa[4] = pack2(v1.x, v1.x); xa[5] = pack2(v1.y, v1.y);
        xa[6] = pack2(v1.z, v1.z); xa[7] = pack2(v1.w, v1.w);
    }
    {
        const float4* xp = (const float4*)(x + (size_t)point1 * D);
        float4 v0 = xp[0], v1 = xp[1];
        xb[0] = pack2(v0.x, v0.x); xb[1] = pack2(v0.y, v0.y);
        xb[2] = pack2(v0.z, v0.z); xb[3] = pack2(v0.w, v0.w);
        xb[4] = pack2(v1.x, v1.x); xb[5] = pack2(v1.y, v1.y);
        xb[6] = pack2(v1.z, v1.z); xb[7] = pack2(v1.w, v1.w);
    }
    const u64 NEG2 = pack2(-2.0f, -2.0f);

    float bestA = FLT_BIG, bestB = FLT_BIG;
    int   idxA  = 0,       idxB  = 0;

    #pragma unroll 4
    for (int p = 0; p < PAIRS; p++) {
        const ulonglong2* q = (const ulonglong2*)&s_pair[p * D];
        ulonglong2 q0 = q[0], q1 = q[1], q2 = q[2], q3 = q[3];
        u64 nrm = s_norm[p];

        // dot = sum_k x_k*a_k, ascending-k sequential FMA chain (reference order)
        u64 accA = fma2(xa[0], q0.x, 0ull);
        u64 accB = fma2(xb[0], q0.x, 0ull);
        accA = fma2(xa[1], q0.y, accA);  accB = fma2(xb[1], q0.y, accB);
        accA = fma2(xa[2], q1.x, accA);  accB = fma2(xb[2], q1.x, accB);
        accA = fma2(xa[3], q1.y, accA);  accB = fma2(xb[3], q1.y, accB);
        accA = fma2(xa[4], q2.x, accA);  accB = fma2(xb[4], q2.x, accB);
        accA = fma2(xa[5], q2.y, accA);  accB = fma2(xb[5], q2.y, accB);
        accA = fma2(xa[6], q3.x, accA);  accB = fma2(xb[6], q3.x, accB);
        accA = fma2(xa[7], q3.y, accA);  accB = fma2(xb[7], q3.y, accB);
        // score = fma(dot, -2, norm): -2*dot is exact (pow2 scale) => same
        // rounding as reference's mul-then-add.
        u64 sA = fma2(accA, NEG2, nrm);
        u64 sB = fma2(accB, NEG2, nrm);

        const int ib = abase + 2 * p;
        {
            float slo, shi; unpack2(sA, slo, shi);
            float m = fminf(slo, shi);                 // tie -> value equal either way
            int  ii = (shi < slo) ? ib + 1 : ib;       // tie -> even (lower) index
            if (m < bestA) { bestA = m; idxA = ii; }   // tie -> earlier index
        }
        {
            float slo, shi; unpack2(sB, slo, shi);
            float m = fminf(slo, shi);
            int  ii = (shi < slo) ? ib + 1 : ib;
            if (m < bestB) { bestB = m; idxB = ii; }
        }
    }

    // fold this chunk's winner into the global per-point best
    u64 keyA = ((u64)sortable(bestA) << 32) | (unsigned)idxA;
    u64 keyB = ((u64)sortable(bestB) << 32) | (unsigned)idxB;
    atomicMin(&g_best[point0], keyA);
    atomicMin(&g_best[point1], keyB);
}

__global__ __launch_bounds__(128) void finalize_kernel(const float* __restrict__ x,
                                                       const float* __restrict__ anchors,
                                                       const float* __restrict__ sa_tab,
                                                       const float* __restrict__ sb_tab,
                                                       const int* __restrict__ t,
                                                       float* __restrict__ out) {
    const int point = blockIdx.x * blockDim.x + threadIdx.x;
    if (point >= P_TOTAL) return;

    const int bidx = (int)(unsigned)(g_best[point] & 0xFFFFFFFFull);

    const int b  = point / NQ;
    const int tb = t[b];
    const float sa = sa_tab[tb];
    const float sb = sb_tab[tb];

    const float4* xp = (const float4*)(x + (size_t)point * D);
    const float4* ap = (const float4*)(anchors + (size_t)bidx * D);
    float4 x0 = xp[0], x1 = xp[1];
    float4 a0 = ap[0], a1 = ap[1];
    float4 o0, o1;
    // out = round(sa*x) + round(sb*a), no FMA contraction (reference order)
    o0.x = __fadd_rn(__fmul_rn(sa, x0.x), __fmul_rn(sb, a0.x));
    o0.y = __fadd_rn(__fmul_rn(sa, x0.y), __fmul_rn(sb, a0.y));
    o0.z = __fadd_rn(__fmul_rn(sa, x0.z), __fmul_rn(sb, a0.z));
    o0.w = __fadd_rn(__fmul_rn(sa, x0.w), __fmul_rn(sb, a0.w));
    o1.x = __fadd_rn(__fmul_rn(sa, x1.x), __fmul_rn(sb, a1.x));
    o1.y = __fadd_rn(__fmul_rn(sa, x1.y), __fmul_rn(sb, a1.y));
    o1.z = __fadd_rn(__fmul_rn(sa, x1.z), __fmul_rn(sb, a1.z));
    o1.w = __fadd_rn(__fmul_rn(sa, x1.w), __fmul_rn(sb, a1.w));

    float4* op = (float4*)(out + (size_t)point * D);
    op[0] = o0; op[1] = o1;
}

extern "C" void kernel_launch(void* const* d_in, const int* in_sizes, int n_in,
                              void* d_out, int out_size) {
    const float* x       = (const float*)d_in[0];  // [16,2048,4,2]
    const float* anchors = (const float*)d_in[1];  // [8192,4,2]
    const float* sa_tab  = (const float*)d_in[2];  // [1000]
    const float* sb_tab  = (const float*)d_in[3];  // [1000]
    const int*   t       = (const int*)d_in[4];    // [16]
    float*       out     = (float*)d_out;          // [16,2048,4,2]

    init_kernel<<<(P_TOTAL + TPB - 1) / TPB, TPB>>>();
    scan_kernel<<<NPG * NCHUNK, TPB>>>(x, anchors);
    finalize_kernel<<<P_TOTAL / 128, 128>>>(x, anchors, sa_tab, sb_tab, t, out);
}